// round 10
// baseline (speedup 1.0000x reference)
#include <cuda_runtime.h>
#include <cstdint>
#include <math.h>

#define PARTITIONABLE 1
#define BP 161   // padded B smem stride

// dims: K=32 B=32 T=64 H=256 E=256 KB=1024 5H=1280
static __device__ float g_emb[2048 * 256];
static __device__ float g_xw [2048 * 1280];
static __device__ float g_xf [2048];
static __device__ float g_hbuf[2][1024 * 256];
static __device__ float g_cbuf[2][1024 * 256];
static __device__ float g_pbuf[2][1024];
static __device__ unsigned g_keys[64][4];
static __device__ float g_gum[64 * 32768];
static __device__ float g_Wb [1280 * 256];
static __device__ float g_d1[2][8 * 1024];
static __device__ float g_d2[2][8 * 1024];
static __device__ volatile unsigned g_flags[128];   // per-block barrier flags

// ---- threefry2x32, 20 rounds ----
__device__ __forceinline__ void tf2x32(unsigned k0, unsigned k1, unsigned x0, unsigned x1,
                                       unsigned &o0, unsigned &o1) {
    unsigned ks2 = k0 ^ k1 ^ 0x1BD11BDAu;
    x0 += k0; x1 += k1;
#define TFR(r) { x0 += x1; x1 = (x1 << r) | (x1 >> (32 - r)); x1 ^= x0; }
    TFR(13) TFR(15) TFR(26) TFR(6)  x0 += k1;  x1 += ks2 + 1u;
    TFR(17) TFR(29) TFR(16) TFR(24) x0 += ks2; x1 += k0 + 2u;
    TFR(13) TFR(15) TFR(26) TFR(6)  x0 += k0;  x1 += k1 + 3u;
    TFR(17) TFR(29) TFR(16) TFR(24) x0 += k1;  x1 += ks2 + 4u;
    TFR(13) TFR(15) TFR(26) TFR(6)  x0 += ks2; x1 += k0 + 5u;
#undef TFR
    o0 = x0; o1 = x1;
}

__device__ __forceinline__ unsigned rbits32(unsigned k0, unsigned k1, unsigned n, unsigned half) {
    unsigned b0, b1;
#if PARTITIONABLE
    (void)half; tf2x32(k0, k1, 0u, n, b0, b1); return b0 ^ b1;
#else
    if (n < half) { tf2x32(k0, k1, n, n + half, b0, b1); return b0; }
    else          { tf2x32(k0, k1, n - half, n, b0, b1); return b1; }
#endif
}

__device__ __forceinline__ float bits_to_unit(unsigned bits) {
    return __uint_as_float((bits >> 9) | 0x3F800000u) - 1.0f;
}

__device__ __forceinline__ float xla_erfinv(float x) {
    float w = -log1pf(-__fmul_rn(x, x));
    float p;
    if (w < 5.0f) {
        w -= 2.5f;
        p = 2.81022636e-08f;
        p = fmaf(p, w, 3.43273939e-07f);  p = fmaf(p, w, -3.5233877e-06f);
        p = fmaf(p, w, -4.39150654e-06f); p = fmaf(p, w, 0.00021858087f);
        p = fmaf(p, w, -0.00125372503f);  p = fmaf(p, w, -0.00417768164f);
        p = fmaf(p, w, 0.246640727f);     p = fmaf(p, w, 1.50140941f);
    } else {
        w = sqrtf(w) - 3.0f;
        p = -0.000200214257f;
        p = fmaf(p, w, 0.000100950558f);  p = fmaf(p, w, 0.00134934322f);
        p = fmaf(p, w, -0.00367342844f);  p = fmaf(p, w, 0.00573950773f);
        p = fmaf(p, w, -0.0076224613f);   p = fmaf(p, w, 0.00943887047f);
        p = fmaf(p, w, 1.00167406f);      p = fmaf(p, w, 2.83297682f);
    }
    return p * x;
}

__device__ __forceinline__ float sigf(float x) { return 1.0f / (1.0f + expf(-x)); }

__device__ __forceinline__ float warp_sum(float v) {
    v += __shfl_down_sync(0xffffffffu, v, 16); v += __shfl_down_sync(0xffffffffu, v, 8);
    v += __shfl_down_sync(0xffffffffu, v, 4);  v += __shfl_down_sync(0xffffffffu, v, 2);
    v += __shfl_down_sync(0xffffffffu, v, 1);  return v;
}

__global__ void k_keys() {
    int t = threadIdx.x; if (t >= 64) return;
#if PARTITIONABLE
    unsigned kt0, kt1, e0, e1, r0, r1;
    tf2x32(0u, 42u, 0u, (unsigned)t, kt0, kt1);
    tf2x32(kt0, kt1, 0u, 0u, e0, e1);
    tf2x32(kt0, kt1, 0u, 1u, r0, r1);
    g_keys[t][0] = e0; g_keys[t][1] = e1; g_keys[t][2] = r0; g_keys[t][3] = r1;
#else
    unsigned kt0, kt1, o0, o1;
    int j = 2 * t;
    if (j < 64) { tf2x32(0u, 42u, (unsigned)j, (unsigned)(j + 64), o0, o1); kt0 = o0; }
    else        { tf2x32(0u, 42u, (unsigned)(j - 64), (unsigned)j, o0, o1); kt0 = o1; }
    j = 2 * t + 1;
    if (j < 64) { tf2x32(0u, 42u, (unsigned)j, (unsigned)(j + 64), o0, o1); kt1 = o0; }
    else        { tf2x32(0u, 42u, (unsigned)(j - 64), (unsigned)j, o0, o1); kt1 = o1; }
    unsigned a0, a1, b0, b1;
    tf2x32(kt0, kt1, 0u, 2u, a0, a1);
    tf2x32(kt0, kt1, 1u, 3u, b0, b1);
    g_keys[t][0] = a0; g_keys[t][1] = b0; g_keys[t][2] = a1; g_keys[t][3] = b1;
#endif
}

__global__ void k_gum() {
    int idx = blockIdx.x * 256 + threadIdx.x;
    int t = idx >> 15;
    int w = idx & 32767;
    int c = w >> 10, ib = w & 1023;
    int i = ib >> 5, b = ib & 31;
    unsigned n = (unsigned)(i * 1024 + b * 32 + c);
    float f = bits_to_unit(rbits32(g_keys[t][2], g_keys[t][3], n, 16384u));
    float u = (f == 0.0f) ? 1.17549435e-38f : f;
    g_gum[idx] = -logf(-logf(u));
}

__global__ void k_prep(const float* __restrict__ W_hh) {
    int idx = blockIdx.x * 256 + threadIdx.x;
    int k = idx & 255, gc = idx >> 8;
    int g = gc / 160, cg = gc % 160;
    int gate = cg >> 5, j = cg & 31;
    g_Wb[idx] = W_hh[(gate * 256 + g * 32 + j) * 256 + k];
}

__global__ void k_init(const float* __restrict__ h0, const float* __restrict__ c0) {
    int i = blockIdx.x * 256 + threadIdx.x;
    g_hbuf[0][i] = h0[i]; g_cbuf[0][i] = c0[i];
    if (i < 128) g_flags[i] = 0u;
}

__global__ void k_emb(const float* __restrict__ obs, const float* __restrict__ win,
                      const float* __restrict__ W_obs, const float* __restrict__ b_obs,
                      const float* __restrict__ W_act, const float* __restrict__ b_act,
                      const float* __restrict__ W_fc, const float* __restrict__ b_fc) {
    int row = blockIdx.x, t = row >> 5, b = row & 31, c = threadIdx.x;
    float acc;
    if (c < 128) {
        const float* x = obs + b * 4096 + t * 64;
        const float* w = W_obs + c * 64;
        acc = b_obs[c];
        #pragma unroll 8
        for (int e = 0; e < 64; e++) acc = fmaf(x[e], w[e], acc);
    } else {
        const float* x = win + b * 3200 + t * 50;
        const float* w = W_act + (c - 128) * 50;
        acc = b_act[c - 128];
        for (int e = 0; e < 50; e++) acc = fmaf(x[e], w[e], acc);
    }
    acc = fmaxf(acc, 0.0f);
    g_emb[row * 256 + c] = acc;
    float xf = warp_sum(acc * W_fc[256 + c]);
    __shared__ float sm[8];
    if ((c & 31) == 0) sm[c >> 5] = xf;
    __syncthreads();
    if (c == 0) {
        float s = 0.0f;
        for (int i = 0; i < 8; i++) s += sm[i];
        g_xf[row] = s + b_fc[0];
    }
}

__global__ void k_gemm0(const float* __restrict__ W, const float* __restrict__ b1,
                        const float* __restrict__ b2) {
    __shared__ float As[16][64], Bs[16][64];
    int tid = threadIdx.x;
    int colBase = blockIdx.x << 6, rowBase = blockIdx.y << 6;
    int lr = tid >> 2, lc = (tid & 3) << 2;
    const float* Ap = g_emb + (rowBase + lr) * 256 + lc;
    const float* Bp = W + (colBase + lr) * 256 + lc;
    float acc[4][4] = {};
    int tx = tid & 15, ty = tid >> 4;
    for (int k0 = 0; k0 < 256; k0 += 16) {
        float4 av = *(const float4*)(Ap + k0);
        float4 bv = *(const float4*)(Bp + k0);
        __syncthreads();
        As[lc][lr] = av.x; As[lc+1][lr] = av.y; As[lc+2][lr] = av.z; As[lc+3][lr] = av.w;
        Bs[lc][lr] = bv.x; Bs[lc+1][lr] = bv.y; Bs[lc+2][lr] = bv.z; Bs[lc+3][lr] = bv.w;
        __syncthreads();
        #pragma unroll
        for (int kk = 0; kk < 16; kk++) {
            float4 a = *(const float4*)&As[kk][ty << 2];
            float4 b = *(const float4*)&Bs[kk][tx << 2];
            acc[0][0]=fmaf(a.x,b.x,acc[0][0]); acc[0][1]=fmaf(a.x,b.y,acc[0][1]);
            acc[0][2]=fmaf(a.x,b.z,acc[0][2]); acc[0][3]=fmaf(a.x,b.w,acc[0][3]);
            acc[1][0]=fmaf(a.y,b.x,acc[1][0]); acc[1][1]=fmaf(a.y,b.y,acc[1][1]);
            acc[1][2]=fmaf(a.y,b.z,acc[1][2]); acc[1][3]=fmaf(a.y,b.w,acc[1][3]);
            acc[2][0]=fmaf(a.z,b.x,acc[2][0]); acc[2][1]=fmaf(a.z,b.y,acc[2][1]);
            acc[2][2]=fmaf(a.z,b.z,acc[2][2]); acc[2][3]=fmaf(a.z,b.w,acc[2][3]);
            acc[3][0]=fmaf(a.w,b.x,acc[3][0]); acc[3][1]=fmaf(a.w,b.y,acc[3][1]);
            acc[3][2]=fmaf(a.w,b.z,acc[3][2]); acc[3][3]=fmaf(a.w,b.w,acc[3][3]);
        }
    }
    int r0 = rowBase + (ty << 2), c0 = colBase + (tx << 2);
    #pragma unroll
    for (int i = 0; i < 4; i++)
        #pragma unroll
        for (int j = 0; j < 4; j++) {
            int cc = c0 + j;
            g_xw[(r0 + i) * 1280 + cc] = acc[i][j] + b1[cc] + b2[cc];
        }
}

// flag-array grid barrier — parallel arrivals, distributed polling (128 blocks, 1/SM)
__device__ __forceinline__ void gbar(int bid, unsigned target) {
    __syncthreads();
    if (threadIdx.x == 0) {
        __threadfence();
        g_flags[bid] = target;
    }
    if (threadIdx.x < 128) {
        while (g_flags[threadIdx.x] < target) { __nanosleep(32); }
        __threadfence();
    }
    __syncthreads();
}

// ===== persistent kernel: all 64 steps; resample prologue + GEMM (B smem-resident) + cell =====
__global__ __launch_bounds__(512, 1) void k_persist(const float* __restrict__ W_fc,
                                                    const float* __restrict__ W_lab,
                                                    float* __restrict__ out,
                                                    const float* __restrict__ b_lab) {
    extern __shared__ float smem[];
    float* Bsm = smem;                    // 256*BP = 41216
    float* Asm = smem + 41216;            // 2*16*64 = 2048
    float* sv  = smem + 43264;
    float* sp1 = sv + 1024;
    float* slg = sp1 + 1024;
    float* spn = slg + 1024;
    float* ssv = spn + 1024;
    __shared__ int   sfl[1024];
    __shared__ float smx[32], sls[32], ss2[32];

    int tid = threadIdx.x;
    int g = blockIdx.x;
    int rowBase = blockIdx.y << 6;
    int bid = (blockIdx.y << 3) + blockIdx.x;
    bool blk0 = (bid == 0);
    int w = tid >> 5, j = tid & 31;
    int hc = (g << 5) + j;
    float wfc = W_fc[hc], wlb = W_lab[hc];
    float bl = b_lab[0];

    // load this block's W_hh slice into resident smem (transposed to [k][col])
    {
        const float* Wb = g_Wb + g * 40960;
        for (int idx = tid; idx < 40960; idx += 512) {
            int cg = idx >> 8, k = idx & 255;
            Bsm[k * BP + cg] = Wb[idx];
        }
    }

    int lrow = tid >> 2, lkc = (tid & 3) << 2;

    for (int t = 0; t <= 64; t++) {
        int ib = t & 1, ob = ib ^ 1;

        // ---------- prologue: resample step s = t-1 ----------
        if (t > 0) {
            int s = t - 1;
            int dp = s & 1;
            #pragma unroll
            for (int q = 0; q < 2; q++) {
                int kb = tid + (q << 9);
                float d1 = 0.0f, d2 = 0.0f;
                #pragma unroll
                for (int gg = 0; gg < 8; gg++) {
                    d1 += g_d1[dp][(gg << 10) + kb];
                    d2 += g_d2[dp][(gg << 10) + kb];
                }
                float pprev = (s == 0) ? -3.4657359027997265f : g_pbuf[(s - 1) & 1][kb];
                float v = (d1 + g_xf[s * 32 + (kb & 31)]) + pprev;
                sv[kb] = v; ssv[kb] = d2;
            }
            __syncthreads();
            if (tid < 32) {
                float m = -1e30f;
                for (int k = 0; k < 32; k++) m = fmaxf(m, sv[k * 32 + tid]);
                float sum = 0.0f;
                for (int k = 0; k < 32; k++) sum += expf(sv[k * 32 + tid] - m);
                smx[tid] = m; sls[tid] = logf(sum);
            }
            __syncthreads();
            #pragma unroll
            for (int q = 0; q < 2; q++) {
                int kb = tid + (q << 9), b = kb & 31;
                float p1 = (sv[kb] - smx[b]) - sls[b];
                sp1[kb] = p1;
                slg[kb] = logf(0.5f * expf(p1) + 0.015625f);
            }
            __syncthreads();
            const float* gum = g_gum + s * 32768;
            #pragma unroll
            for (int q = 0; q < 2; q++) {
                int kb = tid + (q << 9), b = kb & 31;
                float best = -1e38f; int bi = 0;
                #pragma unroll 4
                for (int c = 0; c < 32; c++) {
                    float val = slg[c * 32 + b] + gum[c * 1024 + kb];
                    if (val > best) { best = val; bi = c; }
                }
                int fl = b + bi * 32;
                sfl[kb] = fl;
                float pu = expf(sp1[fl]);
                spn[kb] = logf(pu / (0.5f * pu + 0.015625f));
            }
            __syncthreads();
            if (tid < 32) {
                float m = -1e30f;
                for (int k = 0; k < 32; k++) m = fmaxf(m, spn[k * 32 + tid]);
                float sum = 0.0f;
                for (int k = 0; k < 32; k++) sum += expf(spn[k * 32 + tid] - m);
                ss2[tid] = logf(sum) + m;
            }
            __syncthreads();
            float pnn[2];
            #pragma unroll
            for (int q = 0; q < 2; q++) {
                int kb = tid + (q << 9), b = kb & 31;
                pnn[q] = spn[kb] - ss2[b];
                g_pbuf[s & 1][kb] = pnn[q];
            }
            __syncthreads();
            #pragma unroll
            for (int q = 0; q < 2; q++) {
                int kb = tid + (q << 9);
                spn[kb] = pnn[q];
            }
            __syncthreads();
            if (blk0) {
                #pragma unroll
                for (int q = 0; q < 2; q++) {
                    int kb = tid + (q << 9);
                    out[2048 + s * 1024 + kb] = 1.0f / (1.0f + expf(-(ssv[sfl[kb]] + bl)));
                }
                if (tid < 32) {
                    float acc = 0.0f;
                    for (int k = 0; k < 32; k++)
                        acc += expf(spn[k * 32 + tid]) * ssv[sfl[k * 32 + tid]];
                    out[s * 32 + tid] = 1.0f / (1.0f + expf(-(acc + bl)));
                }
            }
        } else {
            sfl[tid] = tid; sfl[tid + 512] = tid + 512;
        }
        __syncthreads();

        if (t == 64) break;

        // ---------- prefetch epilogue operands (consumed after GEMM) ----------
        float pre_cp[4], pre_xw[4][5];
        {
            #pragma unroll
            for (int r = 0; r < 4; r++) {
                int kb = rowBase + (w << 2) + r;
                int b = kb & 31;
                const float* xw = g_xw + (t * 32 + b) * 1280;
                pre_cp[r]  = g_cbuf[ib][sfl[kb] * 256 + hc];
                #pragma unroll
                for (int gg = 0; gg < 5; gg++) pre_xw[r][gg] = xw[gg * 256 + hc];
            }
        }
        unsigned ke0 = g_keys[t][0], ke1 = g_keys[t][1];
        unsigned ebits[4];

        // ---------- recurrent GEMM: A staged (gathered), B resident in smem ----------
        const float* Ab = g_hbuf[ib] + sfl[rowBase + lrow] * 256 + lkc;   // tid<256 use
        float4 aP = make_float4(0, 0, 0, 0);
        if (tid < 256) {
            aP = *(const float4*)(Ab);
            Asm[(lkc + 0) * 64 + lrow] = aP.x; Asm[(lkc + 1) * 64 + lrow] = aP.y;
            Asm[(lkc + 2) * 64 + lrow] = aP.z; Asm[(lkc + 3) * 64 + lrow] = aP.w;
        }
        __syncthreads();

        float acc[4][5] = {};
        for (int kt = 0; kt < 16; kt++) {
            int buf = kt & 1;
            if (kt < 15 && tid < 256) aP = *(const float4*)(Ab + ((kt + 1) << 4));
            if (kt < 4) {
                // in-loop Gaussian-noise bits: pure ALU work slotted into idle issue slots
                int kb = rowBase + (w << 2) + kt;
                ebits[kt] = rbits32(ke0, ke1, (unsigned)(kb * 256 + hc), 131072u);
            }
            const float* Bk = Bsm + (kt << 4) * BP;
            const float* Ak = Asm + buf * 1024;
            #pragma unroll
            for (int kk = 0; kk < 16; kk++) {
                float4 a = *(const float4*)&Ak[kk * 64 + (w << 2)];
                float b0 = Bk[kk * BP + j];
                float b1 = Bk[kk * BP + 32 + j];
                float b2 = Bk[kk * BP + 64 + j];
                float b3 = Bk[kk * BP + 96 + j];
                float b4 = Bk[kk * BP + 128 + j];
                float av[4] = {a.x, a.y, a.z, a.w};
                #pragma unroll
                for (int r = 0; r < 4; r++) {
                    acc[r][0] = fmaf(av[r], b0, acc[r][0]);
                    acc[r][1] = fmaf(av[r], b1, acc[r][1]);
                    acc[r][2] = fmaf(av[r], b2, acc[r][2]);
                    acc[r][3] = fmaf(av[r], b3, acc[r][3]);
                    acc[r][4] = fmaf(av[r], b4, acc[r][4]);
                }
            }
            if (kt < 15) {
                __syncthreads();
                int nb = buf ^ 1;
                if (tid < 256) {
                    float* An = Asm + nb * 1024;
                    An[(lkc + 0) * 64 + lrow] = aP.x; An[(lkc + 1) * 64 + lrow] = aP.y;
                    An[(lkc + 2) * 64 + lrow] = aP.z; An[(lkc + 3) * 64 + lrow] = aP.w;
                }
                __syncthreads();
            }
        }

        // ---------- fused LSTM cell epilogue ----------
        int wp = t & 1;
        #pragma unroll
        for (int r = 0; r < 4; r++) {
            int kb = rowBase + (w << 2) + r;
            float gi = acc[r][0] + pre_xw[r][0];
            float gf = acc[r][1] + pre_xw[r][1];
            float gg = acc[r][2] + pre_xw[r][2];
            float go = acc[r][3] + pre_xw[r][3];
            float gv = acc[r][4] + pre_xw[r][4];
            float c1 = sigf(gf) * pre_cp[r] + sigf(gi) * tanhf(gg);
            float sp = fmaxf(gv, 0.0f) + log1pf(expf(-fabsf(gv)));
            // Gaussian eps from in-loop bits (identical chain to old k_eps)
            float f01 = bits_to_unit(ebits[r]);
            float u = fmaxf(-0.99999994f, __fadd_rn(__fmul_rn(f01, 1.99999994f), -0.99999994f));
            float eps = 1.41421356f * xla_erfinv(u);
            c1 += eps * sp;
            float h1 = sigf(go) * tanhf(c1);
            g_hbuf[ob][kb * 256 + hc] = h1;
            g_cbuf[ob][kb * 256 + hc] = c1;
            float d1 = warp_sum(h1 * wfc);
            float d2 = warp_sum(h1 * wlb);
            if (j == 0) { g_d1[wp][(g << 10) + kb] = d1; g_d2[wp][(g << 10) + kb] = d2; }
        }

        gbar(bid, (unsigned)(t + 1));
    }
}

extern "C" void kernel_launch(void* const* d_in, const int* in_sizes, int n_in,
                              void* d_out, int out_size) {
    const float* obs    = (const float*)d_in[0];
    const float* win    = (const float*)d_in[1];
    const float* W_obs  = (const float*)d_in[2];
    const float* b_obs  = (const float*)d_in[3];
    const float* W_act  = (const float*)d_in[4];
    const float* b_act  = (const float*)d_in[5];
    const float* W_ih   = (const float*)d_in[6];
    const float* b_ih   = (const float*)d_in[7];
    const float* W_hh   = (const float*)d_in[8];
    const float* b_hh   = (const float*)d_in[9];
    const float* W_fc   = (const float*)d_in[10];
    const float* b_fc   = (const float*)d_in[11];
    const float* W_lab  = (const float*)d_in[12];
    const float* b_lab  = (const float*)d_in[13];
    const float* h0     = (const float*)d_in[14];
    const float* c0     = (const float*)d_in[15];
    float* out = (float*)d_out;

    size_t smem_bytes = (size_t)(41216 + 2048 + 5 * 1024) * sizeof(float);   // 193536
    cudaFuncSetAttribute(k_persist, cudaFuncAttributeMaxDynamicSharedMemorySize,
                         (int)smem_bytes);

    k_keys<<<1, 64>>>();
    k_init<<<1024, 256>>>(h0, c0);
    k_gum<<<8192, 256>>>();
    k_prep<<<1280, 256>>>(W_hh);
    k_emb<<<2048, 256>>>(obs, win, W_obs, b_obs, W_act, b_act, W_fc, b_fc);
    k_gemm0<<<dim3(20, 32), 256>>>(W_ih, b_ih, b_hh);
    k_persist<<<dim3(8, 16), 512, smem_bytes>>>(W_fc, W_lab, out, b_lab);
}

// round 11
// speedup vs baseline: 1.1293x; 1.1293x over previous
#include <cuda_runtime.h>
#include <cstdint>
#include <math.h>

#define PARTITIONABLE 1
#define BP 161   // padded B smem stride

// dims: K=32 B=32 T=64 H=256 E=256 KB=1024 5H=1280
static __device__ float g_emb[2048 * 256];
static __device__ float g_xw [2048 * 1280];
static __device__ float g_xf [2048];
static __device__ float g_hbuf[2][1024 * 256];
static __device__ float g_cbuf[2][1024 * 256];
static __device__ float g_pbuf[2][1024];
static __device__ unsigned g_keys[64][4];
static __device__ float g_gum[64 * 32768];
static __device__ float g_Wb [1280 * 256];
static __device__ float g_d1[2][8 * 1024];
static __device__ float g_d2[2][8 * 1024];
static __device__ unsigned g_barA;
static __device__ unsigned g_barG;

// ---- threefry2x32, 20 rounds ----
__device__ __forceinline__ void tf2x32(unsigned k0, unsigned k1, unsigned x0, unsigned x1,
                                       unsigned &o0, unsigned &o1) {
    unsigned ks2 = k0 ^ k1 ^ 0x1BD11BDAu;
    x0 += k0; x1 += k1;
#define TFR(r) { x0 += x1; x1 = (x1 << r) | (x1 >> (32 - r)); x1 ^= x0; }
    TFR(13) TFR(15) TFR(26) TFR(6)  x0 += k1;  x1 += ks2 + 1u;
    TFR(17) TFR(29) TFR(16) TFR(24) x0 += ks2; x1 += k0 + 2u;
    TFR(13) TFR(15) TFR(26) TFR(6)  x0 += k0;  x1 += k1 + 3u;
    TFR(17) TFR(29) TFR(16) TFR(24) x0 += k1;  x1 += ks2 + 4u;
    TFR(13) TFR(15) TFR(26) TFR(6)  x0 += ks2; x1 += k0 + 5u;
#undef TFR
    o0 = x0; o1 = x1;
}

__device__ __forceinline__ unsigned rbits32(unsigned k0, unsigned k1, unsigned n, unsigned half) {
    unsigned b0, b1;
#if PARTITIONABLE
    (void)half; tf2x32(k0, k1, 0u, n, b0, b1); return b0 ^ b1;
#else
    if (n < half) { tf2x32(k0, k1, n, n + half, b0, b1); return b0; }
    else          { tf2x32(k0, k1, n - half, n, b0, b1); return b1; }
#endif
}

__device__ __forceinline__ float bits_to_unit(unsigned bits) {
    return __uint_as_float((bits >> 9) | 0x3F800000u) - 1.0f;
}

__device__ __forceinline__ float xla_erfinv(float x) {
    float w = -log1pf(-__fmul_rn(x, x));
    float p;
    if (w < 5.0f) {
        w -= 2.5f;
        p = 2.81022636e-08f;
        p = fmaf(p, w, 3.43273939e-07f);  p = fmaf(p, w, -3.5233877e-06f);
        p = fmaf(p, w, -4.39150654e-06f); p = fmaf(p, w, 0.00021858087f);
        p = fmaf(p, w, -0.00125372503f);  p = fmaf(p, w, -0.00417768164f);
        p = fmaf(p, w, 0.246640727f);     p = fmaf(p, w, 1.50140941f);
    } else {
        w = sqrtf(w) - 3.0f;
        p = -0.000200214257f;
        p = fmaf(p, w, 0.000100950558f);  p = fmaf(p, w, 0.00134934322f);
        p = fmaf(p, w, -0.00367342844f);  p = fmaf(p, w, 0.00573950773f);
        p = fmaf(p, w, -0.0076224613f);   p = fmaf(p, w, 0.00943887047f);
        p = fmaf(p, w, 1.00167406f);      p = fmaf(p, w, 2.83297682f);
    }
    return p * x;
}

__device__ __forceinline__ float sigf(float x) { return 1.0f / (1.0f + expf(-x)); }

__device__ __forceinline__ float warp_sum(float v) {
    v += __shfl_down_sync(0xffffffffu, v, 16); v += __shfl_down_sync(0xffffffffu, v, 8);
    v += __shfl_down_sync(0xffffffffu, v, 4);  v += __shfl_down_sync(0xffffffffu, v, 2);
    v += __shfl_down_sync(0xffffffffu, v, 1);  return v;
}

__global__ void k_keys() {
    int t = threadIdx.x; if (t >= 64) return;
#if PARTITIONABLE
    unsigned kt0, kt1, e0, e1, r0, r1;
    tf2x32(0u, 42u, 0u, (unsigned)t, kt0, kt1);
    tf2x32(kt0, kt1, 0u, 0u, e0, e1);
    tf2x32(kt0, kt1, 0u, 1u, r0, r1);
    g_keys[t][0] = e0; g_keys[t][1] = e1; g_keys[t][2] = r0; g_keys[t][3] = r1;
#else
    unsigned kt0, kt1, o0, o1;
    int j = 2 * t;
    if (j < 64) { tf2x32(0u, 42u, (unsigned)j, (unsigned)(j + 64), o0, o1); kt0 = o0; }
    else        { tf2x32(0u, 42u, (unsigned)(j - 64), (unsigned)j, o0, o1); kt0 = o1; }
    j = 2 * t + 1;
    if (j < 64) { tf2x32(0u, 42u, (unsigned)j, (unsigned)(j + 64), o0, o1); kt1 = o0; }
    else        { tf2x32(0u, 42u, (unsigned)(j - 64), (unsigned)j, o0, o1); kt1 = o1; }
    unsigned a0, a1, b0, b1;
    tf2x32(kt0, kt1, 0u, 2u, a0, a1);
    tf2x32(kt0, kt1, 1u, 3u, b0, b1);
    g_keys[t][0] = a0; g_keys[t][1] = b0; g_keys[t][2] = a1; g_keys[t][3] = b1;
#endif
}

__global__ void k_gum() {
    int idx = blockIdx.x * 256 + threadIdx.x;
    int t = idx >> 15;
    int w = idx & 32767;
    int c = w >> 10, ib = w & 1023;
    int i = ib >> 5, b = ib & 31;
    unsigned n = (unsigned)(i * 1024 + b * 32 + c);
    float f = bits_to_unit(rbits32(g_keys[t][2], g_keys[t][3], n, 16384u));
    float u = (f == 0.0f) ? 1.17549435e-38f : f;
    g_gum[idx] = -logf(-logf(u));
}

__global__ void k_prep(const float* __restrict__ W_hh) {
    int idx = blockIdx.x * 256 + threadIdx.x;
    int k = idx & 255, gc = idx >> 8;
    int g = gc / 160, cg = gc % 160;
    int gate = cg >> 5, j = cg & 31;
    g_Wb[idx] = W_hh[(gate * 256 + g * 32 + j) * 256 + k];
}

__global__ void k_init(const float* __restrict__ h0, const float* __restrict__ c0) {
    int i = blockIdx.x * 256 + threadIdx.x;
    g_hbuf[0][i] = h0[i]; g_cbuf[0][i] = c0[i];
    if (i == 0) { g_barA = 0u; g_barG = 0u; }
}

__global__ void k_emb(const float* __restrict__ obs, const float* __restrict__ win,
                      const float* __restrict__ W_obs, const float* __restrict__ b_obs,
                      const float* __restrict__ W_act, const float* __restrict__ b_act,
                      const float* __restrict__ W_fc, const float* __restrict__ b_fc) {
    int row = blockIdx.x, t = row >> 5, b = row & 31, c = threadIdx.x;
    float acc;
    if (c < 128) {
        const float* x = obs + b * 4096 + t * 64;
        const float* w = W_obs + c * 64;
        acc = b_obs[c];
        #pragma unroll 8
        for (int e = 0; e < 64; e++) acc = fmaf(x[e], w[e], acc);
    } else {
        const float* x = win + b * 3200 + t * 50;
        const float* w = W_act + (c - 128) * 50;
        acc = b_act[c - 128];
        for (int e = 0; e < 50; e++) acc = fmaf(x[e], w[e], acc);
    }
    acc = fmaxf(acc, 0.0f);
    g_emb[row * 256 + c] = acc;
    float xf = warp_sum(acc * W_fc[256 + c]);
    __shared__ float sm[8];
    if ((c & 31) == 0) sm[c >> 5] = xf;
    __syncthreads();
    if (c == 0) {
        float s = 0.0f;
        for (int i = 0; i < 8; i++) s += sm[i];
        g_xf[row] = s + b_fc[0];
    }
}

__global__ void k_gemm0(const float* __restrict__ W, const float* __restrict__ b1,
                        const float* __restrict__ b2) {
    __shared__ float As[16][64], Bs[16][64];
    int tid = threadIdx.x;
    int colBase = blockIdx.x << 6, rowBase = blockIdx.y << 6;
    int lr = tid >> 2, lc = (tid & 3) << 2;
    const float* Ap = g_emb + (rowBase + lr) * 256 + lc;
    const float* Bp = W + (colBase + lr) * 256 + lc;
    float acc[4][4] = {};
    int tx = tid & 15, ty = tid >> 4;
    for (int k0 = 0; k0 < 256; k0 += 16) {
        float4 av = *(const float4*)(Ap + k0);
        float4 bv = *(const float4*)(Bp + k0);
        __syncthreads();
        As[lc][lr] = av.x; As[lc+1][lr] = av.y; As[lc+2][lr] = av.z; As[lc+3][lr] = av.w;
        Bs[lc][lr] = bv.x; Bs[lc+1][lr] = bv.y; Bs[lc+2][lr] = bv.z; Bs[lc+3][lr] = bv.w;
        __syncthreads();
        #pragma unroll
        for (int kk = 0; kk < 16; kk++) {
            float4 a = *(const float4*)&As[kk][ty << 2];
            float4 b = *(const float4*)&Bs[kk][tx << 2];
            acc[0][0]=fmaf(a.x,b.x,acc[0][0]); acc[0][1]=fmaf(a.x,b.y,acc[0][1]);
            acc[0][2]=fmaf(a.x,b.z,acc[0][2]); acc[0][3]=fmaf(a.x,b.w,acc[0][3]);
            acc[1][0]=fmaf(a.y,b.x,acc[1][0]); acc[1][1]=fmaf(a.y,b.y,acc[1][1]);
            acc[1][2]=fmaf(a.y,b.z,acc[1][2]); acc[1][3]=fmaf(a.y,b.w,acc[1][3]);
            acc[2][0]=fmaf(a.z,b.x,acc[2][0]); acc[2][1]=fmaf(a.z,b.y,acc[2][1]);
            acc[2][2]=fmaf(a.z,b.z,acc[2][2]); acc[2][3]=fmaf(a.z,b.w,acc[2][3]);
            acc[3][0]=fmaf(a.w,b.x,acc[3][0]); acc[3][1]=fmaf(a.w,b.y,acc[3][1]);
            acc[3][2]=fmaf(a.w,b.z,acc[3][2]); acc[3][3]=fmaf(a.w,b.w,acc[3][3]);
        }
    }
    int r0 = rowBase + (ty << 2), c0 = colBase + (tx << 2);
    #pragma unroll
    for (int i = 0; i < 4; i++)
        #pragma unroll
        for (int j = 0; j < 4; j++) {
            int cc = c0 + j;
            g_xw[(r0 + i) * 1280 + cc] = acc[i][j] + b1[cc] + b2[cc];
        }
}

// software grid barrier — all 128 blocks co-resident (1 block/SM)  [round-9 proven design]
__device__ __forceinline__ void gbar(unsigned target) {
    __syncthreads();
    if (threadIdx.x == 0) {
        __threadfence();
        if (atomicAdd(&g_barA, 1u) == 127u) {
            g_barA = 0u;
            __threadfence();
            atomicExch(&g_barG, target);
        } else {
            while (atomicAdd(&g_barG, 0u) < target) { __nanosleep(64); }
        }
        __threadfence();
    }
    __syncthreads();
}

// ===== persistent kernel: all 64 steps; resample prologue + GEMM (B smem-resident) + cell =====
__global__ __launch_bounds__(512, 1) void k_persist(const float* __restrict__ W_fc,
                                                    const float* __restrict__ W_lab,
                                                    float* __restrict__ out,
                                                    const float* __restrict__ b_lab) {
    extern __shared__ float smem[];
    float* Bsm = smem;                    // 256*BP = 41216
    float* Asm = smem + 41216;            // 2*16*64 = 2048
    float* sv  = smem + 43264;
    float* sp1 = sv + 1024;
    float* slg = sp1 + 1024;
    float* spn = slg + 1024;
    float* ssv = spn + 1024;
    __shared__ int   sfl[1024];
    __shared__ float smx[32], sls[32], ss2[32];

    int tid = threadIdx.x;
    int g = blockIdx.x;
    int rowBase = blockIdx.y << 6;
    bool blk0 = (blockIdx.x == 0) && (blockIdx.y == 0);
    int w = tid >> 5, j = tid & 31;
    int hc = (g << 5) + j;
    float wfc = W_fc[hc], wlb = W_lab[hc];
    float bl = b_lab[0];

    // load this block's W_hh slice into resident smem (transposed to [k][col])
    {
        const float* Wb = g_Wb + g * 40960;
        for (int idx = tid; idx < 40960; idx += 512) {
            int cg = idx >> 8, k = idx & 255;
            Bsm[k * BP + cg] = Wb[idx];
        }
    }

    int lrow = tid >> 2, lkc = (tid & 3) << 2;

    for (int t = 0; t <= 64; t++) {
        int ib = t & 1, ob = ib ^ 1;

        // ---------- prologue: resample step s = t-1 ----------
        if (t > 0) {
            int s = t - 1;
            int dp = s & 1;
            #pragma unroll
            for (int q = 0; q < 2; q++) {
                int kb = tid + (q << 9);
                float d1 = 0.0f, d2 = 0.0f;
                #pragma unroll
                for (int gg = 0; gg < 8; gg++) {
                    d1 += g_d1[dp][(gg << 10) + kb];
                    d2 += g_d2[dp][(gg << 10) + kb];
                }
                float pprev = (s == 0) ? -3.4657359027997265f : g_pbuf[(s - 1) & 1][kb];
                float v = (d1 + g_xf[s * 32 + (kb & 31)]) + pprev;
                sv[kb] = v; ssv[kb] = d2;
            }
            __syncthreads();
            if (tid < 32) {
                float m = -1e30f;
                for (int k = 0; k < 32; k++) m = fmaxf(m, sv[k * 32 + tid]);
                float sum = 0.0f;
                for (int k = 0; k < 32; k++) sum += expf(sv[k * 32 + tid] - m);
                smx[tid] = m; sls[tid] = logf(sum);
            }
            __syncthreads();
            #pragma unroll
            for (int q = 0; q < 2; q++) {
                int kb = tid + (q << 9), b = kb & 31;
                float p1 = (sv[kb] - smx[b]) - sls[b];
                sp1[kb] = p1;
                slg[kb] = logf(0.5f * expf(p1) + 0.015625f);
            }
            __syncthreads();
            const float* gum = g_gum + s * 32768;
            #pragma unroll
            for (int q = 0; q < 2; q++) {
                int kb = tid + (q << 9), b = kb & 31;
                float best = -1e38f; int bi = 0;
                #pragma unroll 4
                for (int c = 0; c < 32; c++) {
                    float val = slg[c * 32 + b] + gum[c * 1024 + kb];
                    if (val > best) { best = val; bi = c; }
                }
                int fl = b + bi * 32;
                sfl[kb] = fl;
                float pu = expf(sp1[fl]);
                spn[kb] = logf(pu / (0.5f * pu + 0.015625f));
            }
            __syncthreads();
            if (tid < 32) {
                float m = -1e30f;
                for (int k = 0; k < 32; k++) m = fmaxf(m, spn[k * 32 + tid]);
                float sum = 0.0f;
                for (int k = 0; k < 32; k++) sum += expf(spn[k * 32 + tid] - m);
                ss2[tid] = logf(sum) + m;
            }
            __syncthreads();
            float pnn[2];
            #pragma unroll
            for (int q = 0; q < 2; q++) {
                int kb = tid + (q << 9), b = kb & 31;
                pnn[q] = spn[kb] - ss2[b];
                g_pbuf[s & 1][kb] = pnn[q];
            }
            __syncthreads();
            #pragma unroll
            for (int q = 0; q < 2; q++) {
                int kb = tid + (q << 9);
                spn[kb] = pnn[q];
            }
            __syncthreads();
            if (blk0) {
                #pragma unroll
                for (int q = 0; q < 2; q++) {
                    int kb = tid + (q << 9);
                    out[2048 + s * 1024 + kb] = 1.0f / (1.0f + expf(-(ssv[sfl[kb]] + bl)));
                }
                if (tid < 32) {
                    float acc = 0.0f;
                    for (int k = 0; k < 32; k++)
                        acc += expf(spn[k * 32 + tid]) * ssv[sfl[k * 32 + tid]];
                    out[s * 32 + tid] = 1.0f / (1.0f + expf(-(acc + bl)));
                }
            }
        } else {
            sfl[tid] = tid; sfl[tid + 512] = tid + 512;
        }
        __syncthreads();

        if (t == 64) break;

        // ---------- prefetch epilogue operands (consumed after GEMM) ----------
        float pre_cp[4], pre_xw[4][5];
        {
            #pragma unroll
            for (int r = 0; r < 4; r++) {
                int kb = rowBase + (w << 2) + r;
                int b = kb & 31;
                const float* xw = g_xw + (t * 32 + b) * 1280;
                pre_cp[r]  = g_cbuf[ib][sfl[kb] * 256 + hc];
                #pragma unroll
                for (int gg = 0; gg < 5; gg++) pre_xw[r][gg] = xw[gg * 256 + hc];
            }
        }
        unsigned ke0 = g_keys[t][0], ke1 = g_keys[t][1];
        unsigned ebits[4];

        // ---------- recurrent GEMM: A staged (gathered), B resident in smem ----------
        const float* Ab = g_hbuf[ib] + sfl[rowBase + lrow] * 256 + lkc;   // tid<256 use
        float4 aP = make_float4(0, 0, 0, 0);
        if (tid < 256) {
            aP = *(const float4*)(Ab);
            Asm[(lkc + 0) * 64 + lrow] = aP.x; Asm[(lkc + 1) * 64 + lrow] = aP.y;
            Asm[(lkc + 2) * 64 + lrow] = aP.z; Asm[(lkc + 3) * 64 + lrow] = aP.w;
        }
        __syncthreads();

        float acc[4][5] = {};
        for (int kt = 0; kt < 16; kt++) {
            int buf = kt & 1;
            if (kt < 15 && tid < 256) aP = *(const float4*)(Ab + ((kt + 1) << 4));
            if (kt < 4) {
                // in-loop Gaussian-noise bits: ALU work in FFMA-idle issue slots
                int kb = rowBase + (w << 2) + kt;
                ebits[kt] = rbits32(ke0, ke1, (unsigned)(kb * 256 + hc), 131072u);
            }
            const float* Bk = Bsm + (kt << 4) * BP;
            const float* Ak = Asm + buf * 1024;
            #pragma unroll
            for (int kk = 0; kk < 16; kk++) {
                float4 a = *(const float4*)&Ak[kk * 64 + (w << 2)];
                float b0 = Bk[kk * BP + j];
                float b1 = Bk[kk * BP + 32 + j];
                float b2 = Bk[kk * BP + 64 + j];
                float b3 = Bk[kk * BP + 96 + j];
                float b4 = Bk[kk * BP + 128 + j];
                float av[4] = {a.x, a.y, a.z, a.w};
                #pragma unroll
                for (int r = 0; r < 4; r++) {
                    acc[r][0] = fmaf(av[r], b0, acc[r][0]);
                    acc[r][1] = fmaf(av[r], b1, acc[r][1]);
                    acc[r][2] = fmaf(av[r], b2, acc[r][2]);
                    acc[r][3] = fmaf(av[r], b3, acc[r][3]);
                    acc[r][4] = fmaf(av[r], b4, acc[r][4]);
                }
            }
            if (kt < 15) {
                __syncthreads();
                int nb = buf ^ 1;
                if (tid < 256) {
                    float* An = Asm + nb * 1024;
                    An[(lkc + 0) * 64 + lrow] = aP.x; An[(lkc + 1) * 64 + lrow] = aP.y;
                    An[(lkc + 2) * 64 + lrow] = aP.z; An[(lkc + 3) * 64 + lrow] = aP.w;
                }
                __syncthreads();
            }
        }

        // ---------- fused LSTM cell epilogue ----------
        int wp = t & 1;
        #pragma unroll
        for (int r = 0; r < 4; r++) {
            int kb = rowBase + (w << 2) + r;
            float gi = acc[r][0] + pre_xw[r][0];
            float gf = acc[r][1] + pre_xw[r][1];
            float gg = acc[r][2] + pre_xw[r][2];
            float go = acc[r][3] + pre_xw[r][3];
            float gv = acc[r][4] + pre_xw[r][4];
            float c1 = sigf(gf) * pre_cp[r] + sigf(gi) * tanhf(gg);
            float sp = fmaxf(gv, 0.0f) + log1pf(expf(-fabsf(gv)));
            // Gaussian eps from in-loop bits (identical chain to old k_eps)
            float f01 = bits_to_unit(ebits[r]);
            float u = fmaxf(-0.99999994f, __fadd_rn(__fmul_rn(f01, 1.99999994f), -0.99999994f));
            float eps = 1.41421356f * xla_erfinv(u);
            c1 += eps * sp;
            float h1 = sigf(go) * tanhf(c1);
            g_hbuf[ob][kb * 256 + hc] = h1;
            g_cbuf[ob][kb * 256 + hc] = c1;
            float d1 = warp_sum(h1 * wfc);
            float d2 = warp_sum(h1 * wlb);
            if (j == 0) { g_d1[wp][(g << 10) + kb] = d1; g_d2[wp][(g << 10) + kb] = d2; }
        }

        gbar((unsigned)(t + 1));
    }
}

extern "C" void kernel_launch(void* const* d_in, const int* in_sizes, int n_in,
                              void* d_out, int out_size) {
    const float* obs    = (const float*)d_in[0];
    const float* win    = (const float*)d_in[1];
    const float* W_obs  = (const float*)d_in[2];
    const float* b_obs  = (const float*)d_in[3];
    const float* W_act  = (const float*)d_in[4];
    const float* b_act  = (const float*)d_in[5];
    const float* W_ih   = (const float*)d_in[6];
    const float* b_ih   = (const float*)d_in[7];
    const float* W_hh   = (const float*)d_in[8];
    const float* b_hh   = (const float*)d_in[9];
    const float* W_fc   = (const float*)d_in[10];
    const float* b_fc   = (const float*)d_in[11];
    const float* W_lab  = (const float*)d_in[12];
    const float* b_lab  = (const float*)d_in[13];
    const float* h0     = (const float*)d_in[14];
    const float* c0     = (const float*)d_in[15];
    float* out = (float*)d_out;

    size_t smem_bytes = (size_t)(41216 + 2048 + 5 * 1024) * sizeof(float);   // 193536
    cudaFuncSetAttribute(k_persist, cudaFuncAttributeMaxDynamicSharedMemorySize,
                         (int)smem_bytes);

    k_keys<<<1, 64>>>();
    k_init<<<1024, 256>>>(h0, c0);
    k_gum<<<8192, 256>>>();
    k_prep<<<1280, 256>>>(W_hh);
    k_emb<<<2048, 256>>>(obs, win, W_obs, b_obs, W_act, b_act, W_fc, b_fc);
    k_gemm0<<<dim3(20, 32), 256>>>(W_ih, b_ih, b_hh);
    k_persist<<<dim3(8, 16), 512, smem_bytes>>>(W_fc, W_lab, out, b_lab);
}

// round 12
// speedup vs baseline: 1.1351x; 1.0051x over previous
#include <cuda_runtime.h>
#include <cstdint>
#include <math.h>

#define PARTITIONABLE 1
#define BP 161   // padded B smem stride

// dims: K=32 B=32 T=64 H=256 E=256 KB=1024 5H=1280
static __device__ float g_emb[2048 * 256];
static __device__ float g_xw [2048 * 1280];
static __device__ float g_xf [2048];
static __device__ float g_hbuf[2][1024 * 256];
static __device__ float g_cbuf[2][1024 * 256];
static __device__ float g_pbuf[2][1024];
static __device__ unsigned g_keys[64][4];
static __device__ float g_gum[64 * 32768];
static __device__ float g_Wb [1280 * 256];
static __device__ float g_d1[2][8 * 1024];
static __device__ float g_d2[2][8 * 1024];
static __device__ unsigned g_barA;
static __device__ unsigned g_barG;

// ---- threefry2x32, 20 rounds ----
__device__ __forceinline__ void tf2x32(unsigned k0, unsigned k1, unsigned x0, unsigned x1,
                                       unsigned &o0, unsigned &o1) {
    unsigned ks2 = k0 ^ k1 ^ 0x1BD11BDAu;
    x0 += k0; x1 += k1;
#define TFR(r) { x0 += x1; x1 = (x1 << r) | (x1 >> (32 - r)); x1 ^= x0; }
    TFR(13) TFR(15) TFR(26) TFR(6)  x0 += k1;  x1 += ks2 + 1u;
    TFR(17) TFR(29) TFR(16) TFR(24) x0 += ks2; x1 += k0 + 2u;
    TFR(13) TFR(15) TFR(26) TFR(6)  x0 += k0;  x1 += k1 + 3u;
    TFR(17) TFR(29) TFR(16) TFR(24) x0 += k1;  x1 += ks2 + 4u;
    TFR(13) TFR(15) TFR(26) TFR(6)  x0 += ks2; x1 += k0 + 5u;
#undef TFR
    o0 = x0; o1 = x1;
}

__device__ __forceinline__ unsigned rbits32(unsigned k0, unsigned k1, unsigned n, unsigned half) {
    unsigned b0, b1;
#if PARTITIONABLE
    (void)half; tf2x32(k0, k1, 0u, n, b0, b1); return b0 ^ b1;
#else
    if (n < half) { tf2x32(k0, k1, n, n + half, b0, b1); return b0; }
    else          { tf2x32(k0, k1, n - half, n, b0, b1); return b1; }
#endif
}

__device__ __forceinline__ float bits_to_unit(unsigned bits) {
    return __uint_as_float((bits >> 9) | 0x3F800000u) - 1.0f;
}

__device__ __forceinline__ float xla_erfinv(float x) {
    float w = -log1pf(-__fmul_rn(x, x));
    float p;
    if (w < 5.0f) {
        w -= 2.5f;
        p = 2.81022636e-08f;
        p = fmaf(p, w, 3.43273939e-07f);  p = fmaf(p, w, -3.5233877e-06f);
        p = fmaf(p, w, -4.39150654e-06f); p = fmaf(p, w, 0.00021858087f);
        p = fmaf(p, w, -0.00125372503f);  p = fmaf(p, w, -0.00417768164f);
        p = fmaf(p, w, 0.246640727f);     p = fmaf(p, w, 1.50140941f);
    } else {
        w = sqrtf(w) - 3.0f;
        p = -0.000200214257f;
        p = fmaf(p, w, 0.000100950558f);  p = fmaf(p, w, 0.00134934322f);
        p = fmaf(p, w, -0.00367342844f);  p = fmaf(p, w, 0.00573950773f);
        p = fmaf(p, w, -0.0076224613f);   p = fmaf(p, w, 0.00943887047f);
        p = fmaf(p, w, 1.00167406f);      p = fmaf(p, w, 2.83297682f);
    }
    return p * x;
}

__device__ __forceinline__ float sigf(float x) { return 1.0f / (1.0f + expf(-x)); }

__device__ __forceinline__ float warp_sum(float v) {
    v += __shfl_down_sync(0xffffffffu, v, 16); v += __shfl_down_sync(0xffffffffu, v, 8);
    v += __shfl_down_sync(0xffffffffu, v, 4);  v += __shfl_down_sync(0xffffffffu, v, 2);
    v += __shfl_down_sync(0xffffffffu, v, 1);  return v;
}

__global__ void k_keys() {
    int t = threadIdx.x; if (t >= 64) return;
#if PARTITIONABLE
    unsigned kt0, kt1, e0, e1, r0, r1;
    tf2x32(0u, 42u, 0u, (unsigned)t, kt0, kt1);
    tf2x32(kt0, kt1, 0u, 0u, e0, e1);
    tf2x32(kt0, kt1, 0u, 1u, r0, r1);
    g_keys[t][0] = e0; g_keys[t][1] = e1; g_keys[t][2] = r0; g_keys[t][3] = r1;
#else
    unsigned kt0, kt1, o0, o1;
    int j = 2 * t;
    if (j < 64) { tf2x32(0u, 42u, (unsigned)j, (unsigned)(j + 64), o0, o1); kt0 = o0; }
    else        { tf2x32(0u, 42u, (unsigned)(j - 64), (unsigned)j, o0, o1); kt0 = o1; }
    j = 2 * t + 1;
    if (j < 64) { tf2x32(0u, 42u, (unsigned)j, (unsigned)(j + 64), o0, o1); kt1 = o0; }
    else        { tf2x32(0u, 42u, (unsigned)(j - 64), (unsigned)j, o0, o1); kt1 = o1; }
    unsigned a0, a1, b0, b1;
    tf2x32(kt0, kt1, 0u, 2u, a0, a1);
    tf2x32(kt0, kt1, 1u, 3u, b0, b1);
    g_keys[t][0] = a0; g_keys[t][1] = b0; g_keys[t][2] = a1; g_keys[t][3] = b1;
#endif
}

__global__ void k_gum() {
    int idx = blockIdx.x * 256 + threadIdx.x;
    int t = idx >> 15;
    int w = idx & 32767;
    int c = w >> 10, ib = w & 1023;
    int i = ib >> 5, b = ib & 31;
    unsigned n = (unsigned)(i * 1024 + b * 32 + c);
    float f = bits_to_unit(rbits32(g_keys[t][2], g_keys[t][3], n, 16384u));
    float u = (f == 0.0f) ? 1.17549435e-38f : f;
    g_gum[idx] = -logf(-logf(u));
}

__global__ void k_prep(const float* __restrict__ W_hh) {
    int idx = blockIdx.x * 256 + threadIdx.x;
    int k = idx & 255, gc = idx >> 8;
    int g = gc / 160, cg = gc % 160;
    int gate = cg >> 5, j = cg & 31;
    g_Wb[idx] = W_hh[(gate * 256 + g * 32 + j) * 256 + k];
}

__global__ void k_init(const float* __restrict__ h0, const float* __restrict__ c0) {
    int i = blockIdx.x * 256 + threadIdx.x;
    g_hbuf[0][i] = h0[i]; g_cbuf[0][i] = c0[i];
    if (i == 0) { g_barA = 0u; g_barG = 0u; }
}

__global__ void k_emb(const float* __restrict__ obs, const float* __restrict__ win,
                      const float* __restrict__ W_obs, const float* __restrict__ b_obs,
                      const float* __restrict__ W_act, const float* __restrict__ b_act,
                      const float* __restrict__ W_fc, const float* __restrict__ b_fc) {
    int row = blockIdx.x, t = row >> 5, b = row & 31, c = threadIdx.x;
    float acc;
    if (c < 128) {
        const float* x = obs + b * 4096 + t * 64;
        const float* w = W_obs + c * 64;
        acc = b_obs[c];
        #pragma unroll 8
        for (int e = 0; e < 64; e++) acc = fmaf(x[e], w[e], acc);
    } else {
        const float* x = win + b * 3200 + t * 50;
        const float* w = W_act + (c - 128) * 50;
        acc = b_act[c - 128];
        for (int e = 0; e < 50; e++) acc = fmaf(x[e], w[e], acc);
    }
    acc = fmaxf(acc, 0.0f);
    g_emb[row * 256 + c] = acc;
    float xf = warp_sum(acc * W_fc[256 + c]);
    __shared__ float sm[8];
    if ((c & 31) == 0) sm[c >> 5] = xf;
    __syncthreads();
    if (c == 0) {
        float s = 0.0f;
        for (int i = 0; i < 8; i++) s += sm[i];
        g_xf[row] = s + b_fc[0];
    }
}

__global__ void k_gemm0(const float* __restrict__ W, const float* __restrict__ b1,
                        const float* __restrict__ b2) {
    __shared__ float As[16][64], Bs[16][64];
    int tid = threadIdx.x;
    int colBase = blockIdx.x << 6, rowBase = blockIdx.y << 6;
    int lr = tid >> 2, lc = (tid & 3) << 2;
    const float* Ap = g_emb + (rowBase + lr) * 256 + lc;
    const float* Bp = W + (colBase + lr) * 256 + lc;
    float acc[4][4] = {};
    int tx = tid & 15, ty = tid >> 4;
    for (int k0 = 0; k0 < 256; k0 += 16) {
        float4 av = *(const float4*)(Ap + k0);
        float4 bv = *(const float4*)(Bp + k0);
        __syncthreads();
        As[lc][lr] = av.x; As[lc+1][lr] = av.y; As[lc+2][lr] = av.z; As[lc+3][lr] = av.w;
        Bs[lc][lr] = bv.x; Bs[lc+1][lr] = bv.y; Bs[lc+2][lr] = bv.z; Bs[lc+3][lr] = bv.w;
        __syncthreads();
        #pragma unroll
        for (int kk = 0; kk < 16; kk++) {
            float4 a = *(const float4*)&As[kk][ty << 2];
            float4 b = *(const float4*)&Bs[kk][tx << 2];
            acc[0][0]=fmaf(a.x,b.x,acc[0][0]); acc[0][1]=fmaf(a.x,b.y,acc[0][1]);
            acc[0][2]=fmaf(a.x,b.z,acc[0][2]); acc[0][3]=fmaf(a.x,b.w,acc[0][3]);
            acc[1][0]=fmaf(a.y,b.x,acc[1][0]); acc[1][1]=fmaf(a.y,b.y,acc[1][1]);
            acc[1][2]=fmaf(a.y,b.z,acc[1][2]); acc[1][3]=fmaf(a.y,b.w,acc[1][3]);
            acc[2][0]=fmaf(a.z,b.x,acc[2][0]); acc[2][1]=fmaf(a.z,b.y,acc[2][1]);
            acc[2][2]=fmaf(a.z,b.z,acc[2][2]); acc[2][3]=fmaf(a.z,b.w,acc[2][3]);
            acc[3][0]=fmaf(a.w,b.x,acc[3][0]); acc[3][1]=fmaf(a.w,b.y,acc[3][1]);
            acc[3][2]=fmaf(a.w,b.z,acc[3][2]); acc[3][3]=fmaf(a.w,b.w,acc[3][3]);
        }
    }
    int r0 = rowBase + (ty << 2), c0 = colBase + (tx << 2);
    #pragma unroll
    for (int i = 0; i < 4; i++)
        #pragma unroll
        for (int j = 0; j < 4; j++) {
            int cc = c0 + j;
            g_xw[(r0 + i) * 1280 + cc] = acc[i][j] + b1[cc] + b2[cc];
        }
}

// software grid barrier — all 128 blocks co-resident (1 block/SM)
__device__ __forceinline__ void gbar(unsigned target) {
    __syncthreads();
    if (threadIdx.x == 0) {
        __threadfence();
        if (atomicAdd(&g_barA, 1u) == 127u) {
            g_barA = 0u;
            __threadfence();
            atomicExch(&g_barG, target);
        } else {
            while (atomicAdd(&g_barG, 0u) < target) { __nanosleep(64); }
        }
        __threadfence();
    }
    __syncthreads();
}

// ===== persistent kernel: all 64 steps; resample prologue + GEMM (B smem-resident) + cell =====
__global__ __launch_bounds__(512, 1) void k_persist(const float* __restrict__ W_fc,
                                                    const float* __restrict__ W_lab,
                                                    float* __restrict__ out,
                                                    const float* __restrict__ b_lab) {
    extern __shared__ float smem[];
    float* Bsm = smem;                    // 256*BP = 41216
    float* Asm = smem + 41216;            // 2*16*64 = 2048
    float* sv  = smem + 43264;
    float* sp1 = sv + 1024;
    float* slg = sp1 + 1024;
    float* spn = slg + 1024;
    float* ssv = spn + 1024;
    __shared__ int   sfl[1024];
    __shared__ float smx[32], sls[32], ss2[32];

    int tid = threadIdx.x;
    int g = blockIdx.x;
    int rowBase = blockIdx.y << 6;
    bool blk0 = (blockIdx.x == 0) && (blockIdx.y == 0);
    int w = tid >> 5, j = tid & 31;
    int hc = (g << 5) + j;
    float wfc = W_fc[hc], wlb = W_lab[hc];
    float bl = b_lab[0];

    // load this block's W_hh slice into resident smem (transposed to [k][col])
    {
        const float* Wb = g_Wb + g * 40960;
        for (int idx = tid; idx < 40960; idx += 512) {
            int cg = idx >> 8, k = idx & 255;
            Bsm[k * BP + cg] = Wb[idx];
        }
    }

    int lrow = tid >> 2, lkc = (tid & 3) << 2;

    // eps bits for step 0 (computed once up front; subsequent steps computed in
    // the barrier-slack window at the tail of the previous iteration)
    unsigned ebits[4];
    {
        unsigned ke0 = g_keys[0][0], ke1 = g_keys[0][1];
        #pragma unroll
        for (int r = 0; r < 4; r++) {
            int kb = rowBase + (w << 2) + r;
            ebits[r] = rbits32(ke0, ke1, (unsigned)(kb * 256 + hc), 131072u);
        }
    }

    for (int t = 0; t <= 64; t++) {
        int ib = t & 1, ob = ib ^ 1;

        // ---------- prologue: resample step s = t-1 ----------
        if (t > 0) {
            int s = t - 1;
            int dp = s & 1;
            #pragma unroll
            for (int q = 0; q < 2; q++) {
                int kb = tid + (q << 9);
                float d1 = 0.0f, d2 = 0.0f;
                #pragma unroll
                for (int gg = 0; gg < 8; gg++) {
                    d1 += g_d1[dp][(gg << 10) + kb];
                    d2 += g_d2[dp][(gg << 10) + kb];
                }
                float pprev = (s == 0) ? -3.4657359027997265f : g_pbuf[(s - 1) & 1][kb];
                float v = (d1 + g_xf[s * 32 + (kb & 31)]) + pprev;
                sv[kb] = v; ssv[kb] = d2;
            }
            __syncthreads();
            if (tid < 32) {
                float m = -1e30f;
                for (int k = 0; k < 32; k++) m = fmaxf(m, sv[k * 32 + tid]);
                float sum = 0.0f;
                for (int k = 0; k < 32; k++) sum += expf(sv[k * 32 + tid] - m);
                smx[tid] = m; sls[tid] = logf(sum);
            }
            __syncthreads();
            #pragma unroll
            for (int q = 0; q < 2; q++) {
                int kb = tid + (q << 9), b = kb & 31;
                float p1 = (sv[kb] - smx[b]) - sls[b];
                sp1[kb] = p1;
                slg[kb] = logf(0.5f * expf(p1) + 0.015625f);
            }
            __syncthreads();
            const float* gum = g_gum + s * 32768;
            #pragma unroll
            for (int q = 0; q < 2; q++) {
                int kb = tid + (q << 9), b = kb & 31;
                float best = -1e38f; int bi = 0;
                #pragma unroll 4
                for (int c = 0; c < 32; c++) {
                    float val = slg[c * 32 + b] + gum[c * 1024 + kb];
                    if (val > best) { best = val; bi = c; }
                }
                int fl = b + bi * 32;
                sfl[kb] = fl;
                float pu = expf(sp1[fl]);
                spn[kb] = logf(pu / (0.5f * pu + 0.015625f));
            }
            __syncthreads();
            if (tid < 32) {
                float m = -1e30f;
                for (int k = 0; k < 32; k++) m = fmaxf(m, spn[k * 32 + tid]);
                float sum = 0.0f;
                for (int k = 0; k < 32; k++) sum += expf(spn[k * 32 + tid] - m);
                ss2[tid] = logf(sum) + m;
            }
            __syncthreads();
            float pnn[2];
            #pragma unroll
            for (int q = 0; q < 2; q++) {
                int kb = tid + (q << 9), b = kb & 31;
                pnn[q] = spn[kb] - ss2[b];
                g_pbuf[s & 1][kb] = pnn[q];
            }
            __syncthreads();
            #pragma unroll
            for (int q = 0; q < 2; q++) {
                int kb = tid + (q << 9);
                spn[kb] = pnn[q];
            }
            __syncthreads();
            if (blk0) {
                #pragma unroll
                for (int q = 0; q < 2; q++) {
                    int kb = tid + (q << 9);
                    out[2048 + s * 1024 + kb] = 1.0f / (1.0f + expf(-(ssv[sfl[kb]] + bl)));
                }
                if (tid < 32) {
                    float acc = 0.0f;
                    for (int k = 0; k < 32; k++)
                        acc += expf(spn[k * 32 + tid]) * ssv[sfl[k * 32 + tid]];
                    out[s * 32 + tid] = 1.0f / (1.0f + expf(-(acc + bl)));
                }
            }
        } else {
            sfl[tid] = tid; sfl[tid + 512] = tid + 512;
        }
        __syncthreads();

        if (t == 64) break;

        // ---------- prefetch epilogue operands (consumed after GEMM) ----------
        float pre_cp[4], pre_xw[4][5];
        {
            #pragma unroll
            for (int r = 0; r < 4; r++) {
                int kb = rowBase + (w << 2) + r;
                int b = kb & 31;
                const float* xw = g_xw + (t * 32 + b) * 1280;
                pre_cp[r]  = g_cbuf[ib][sfl[kb] * 256 + hc];
                #pragma unroll
                for (int gg = 0; gg < 5; gg++) pre_xw[r][gg] = xw[gg * 256 + hc];
            }
        }

        // ---------- recurrent GEMM: A staged (gathered), B resident in smem ----------
        const float* Ab = g_hbuf[ib] + sfl[rowBase + lrow] * 256 + lkc;   // tid<256 use
        float4 aP = make_float4(0, 0, 0, 0);
        if (tid < 256) {
            aP = *(const float4*)(Ab);
            Asm[(lkc + 0) * 64 + lrow] = aP.x; Asm[(lkc + 1) * 64 + lrow] = aP.y;
            Asm[(lkc + 2) * 64 + lrow] = aP.z; Asm[(lkc + 3) * 64 + lrow] = aP.w;
        }
        __syncthreads();

        float acc[4][5] = {};
        for (int kt = 0; kt < 16; kt++) {
            int buf = kt & 1;
            if (kt < 15 && tid < 256) aP = *(const float4*)(Ab + ((kt + 1) << 4));
            const float* Bk = Bsm + (kt << 4) * BP;
            const float* Ak = Asm + buf * 1024;
            #pragma unroll
            for (int kk = 0; kk < 16; kk++) {
                float4 a = *(const float4*)&Ak[kk * 64 + (w << 2)];
                float b0 = Bk[kk * BP + j];
                float b1 = Bk[kk * BP + 32 + j];
                float b2 = Bk[kk * BP + 64 + j];
                float b3 = Bk[kk * BP + 96 + j];
                float b4 = Bk[kk * BP + 128 + j];
                float av[4] = {a.x, a.y, a.z, a.w};
                #pragma unroll
                for (int r = 0; r < 4; r++) {
                    acc[r][0] = fmaf(av[r], b0, acc[r][0]);
                    acc[r][1] = fmaf(av[r], b1, acc[r][1]);
                    acc[r][2] = fmaf(av[r], b2, acc[r][2]);
                    acc[r][3] = fmaf(av[r], b3, acc[r][3]);
                    acc[r][4] = fmaf(av[r], b4, acc[r][4]);
                }
            }
            if (kt < 15) {
                __syncthreads();
                int nb = buf ^ 1;
                if (tid < 256) {
                    float* An = Asm + nb * 1024;
                    An[(lkc + 0) * 64 + lrow] = aP.x; An[(lkc + 1) * 64 + lrow] = aP.y;
                    An[(lkc + 2) * 64 + lrow] = aP.z; An[(lkc + 3) * 64 + lrow] = aP.w;
                }
                __syncthreads();
            }
        }

        // ---------- fused LSTM cell epilogue ----------
        int wp = t & 1;
        #pragma unroll
        for (int r = 0; r < 4; r++) {
            int kb = rowBase + (w << 2) + r;
            float gi = acc[r][0] + pre_xw[r][0];
            float gf = acc[r][1] + pre_xw[r][1];
            float gg = acc[r][2] + pre_xw[r][2];
            float go = acc[r][3] + pre_xw[r][3];
            float gv = acc[r][4] + pre_xw[r][4];
            float c1 = sigf(gf) * pre_cp[r] + sigf(gi) * tanhf(gg);
            float sp = fmaxf(gv, 0.0f) + log1pf(expf(-fabsf(gv)));
            float f01 = bits_to_unit(ebits[r]);
            float u = fmaxf(-0.99999994f, __fadd_rn(__fmul_rn(f01, 1.99999994f), -0.99999994f));
            float eps = 1.41421356f * xla_erfinv(u);
            c1 += eps * sp;
            float h1 = sigf(go) * tanhf(c1);
            g_hbuf[ob][kb * 256 + hc] = h1;
            g_cbuf[ob][kb * 256 + hc] = c1;
            float d1 = warp_sum(h1 * wfc);
            float d2 = warp_sum(h1 * wlb);
            if (j == 0) { g_d1[wp][(g << 10) + kb] = d1; g_d2[wp][(g << 10) + kb] = d2; }
        }

        // ---------- barrier-slack window: eps bits for step t+1 ----------
        if (t < 63) {
            unsigned ke0 = g_keys[t + 1][0], ke1 = g_keys[t + 1][1];
            #pragma unroll
            for (int r = 0; r < 4; r++) {
                int kb = rowBase + (w << 2) + r;
                ebits[r] = rbits32(ke0, ke1, (unsigned)(kb * 256 + hc), 131072u);
            }
        }

        gbar((unsigned)(t + 1));
    }
}

extern "C" void kernel_launch(void* const* d_in, const int* in_sizes, int n_in,
                              void* d_out, int out_size) {
    const float* obs    = (const float*)d_in[0];
    const float* win    = (const float*)d_in[1];
    const float* W_obs  = (const float*)d_in[2];
    const float* b_obs  = (const float*)d_in[3];
    const float* W_act  = (const float*)d_in[4];
    const float* b_act  = (const float*)d_in[5];
    const float* W_ih   = (const float*)d_in[6];
    const float* b_ih   = (const float*)d_in[7];
    const float* W_hh   = (const float*)d_in[8];
    const float* b_hh   = (const float*)d_in[9];
    const float* W_fc   = (const float*)d_in[10];
    const float* b_fc   = (const float*)d_in[11];
    const float* W_lab  = (const float*)d_in[12];
    const float* b_lab  = (const float*)d_in[13];
    const float* h0     = (const float*)d_in[14];
    const float* c0     = (const float*)d_in[15];
    float* out = (float*)d_out;

    size_t smem_bytes = (size_t)(41216 + 2048 + 5 * 1024) * sizeof(float);   // 193536
    cudaFuncSetAttribute(k_persist, cudaFuncAttributeMaxDynamicSharedMemorySize,
                         (int)smem_bytes);

    k_keys<<<1, 64>>>();
    k_init<<<1024, 256>>>(h0, c0);
    k_gum<<<8192, 256>>>();
    k_prep<<<1280, 256>>>(W_hh);
    k_emb<<<2048, 256>>>(obs, win, W_obs, b_obs, W_act, b_act, W_fc, b_fc);
    k_gemm0<<<dim3(20, 32), 256>>>(W_ih, b_ih, b_hh);
    k_persist<<<dim3(8, 16), 512, smem_bytes>>>(W_fc, W_lab, out, b_lab);
}

// round 14
// speedup vs baseline: 1.1440x; 1.0078x over previous
#include <cuda_runtime.h>
#include <cstdint>
#include <math.h>

#define PARTITIONABLE 1
#define BP 161   // padded B smem stride

// dims: K=32 B=32 T=64 H=256 E=256 KB=1024 5H=1280
static __device__ float g_emb[2048 * 256];
static __device__ float g_xw [2048 * 1280];
static __device__ float g_xf [2048];
static __device__ float g_hbuf[2][1024 * 256];
static __device__ float g_cbuf[2][1024 * 256];
static __device__ float g_pbuf[2][1024];
static __device__ unsigned g_keys[64][4];
static __device__ float g_gum[64 * 32768];
static __device__ float g_Wb [1280 * 256];
static __device__ float g_d1[2][8 * 1024];
static __device__ float g_d2[2][8 * 1024];
static __device__ unsigned g_barA;
static __device__ unsigned g_barG;

// ---- threefry2x32, 20 rounds ----
__device__ __forceinline__ void tf2x32(unsigned k0, unsigned k1, unsigned x0, unsigned x1,
                                       unsigned &o0, unsigned &o1) {
    unsigned ks2 = k0 ^ k1 ^ 0x1BD11BDAu;
    x0 += k0; x1 += k1;
#define TFR(r) { x0 += x1; x1 = (x1 << r) | (x1 >> (32 - r)); x1 ^= x0; }
    TFR(13) TFR(15) TFR(26) TFR(6)  x0 += k1;  x1 += ks2 + 1u;
    TFR(17) TFR(29) TFR(16) TFR(24) x0 += ks2; x1 += k0 + 2u;
    TFR(13) TFR(15) TFR(26) TFR(6)  x0 += k0;  x1 += k1 + 3u;
    TFR(17) TFR(29) TFR(16) TFR(24) x0 += k1;  x1 += ks2 + 4u;
    TFR(13) TFR(15) TFR(26) TFR(6)  x0 += ks2; x1 += k0 + 5u;
#undef TFR
    o0 = x0; o1 = x1;
}

__device__ __forceinline__ unsigned rbits32(unsigned k0, unsigned k1, unsigned n, unsigned half) {
    unsigned b0, b1;
#if PARTITIONABLE
    (void)half; tf2x32(k0, k1, 0u, n, b0, b1); return b0 ^ b1;
#else
    if (n < half) { tf2x32(k0, k1, n, n + half, b0, b1); return b0; }
    else          { tf2x32(k0, k1, n - half, n, b0, b1); return b1; }
#endif
}

__device__ __forceinline__ float bits_to_unit(unsigned bits) {
    return __uint_as_float((bits >> 9) | 0x3F800000u) - 1.0f;
}

__device__ __forceinline__ float xla_erfinv(float x) {
    float w = -log1pf(-__fmul_rn(x, x));
    float p;
    if (w < 5.0f) {
        w -= 2.5f;
        p = 2.81022636e-08f;
        p = fmaf(p, w, 3.43273939e-07f);  p = fmaf(p, w, -3.5233877e-06f);
        p = fmaf(p, w, -4.39150654e-06f); p = fmaf(p, w, 0.00021858087f);
        p = fmaf(p, w, -0.00125372503f);  p = fmaf(p, w, -0.00417768164f);
        p = fmaf(p, w, 0.246640727f);     p = fmaf(p, w, 1.50140941f);
    } else {
        w = sqrtf(w) - 3.0f;
        p = -0.000200214257f;
        p = fmaf(p, w, 0.000100950558f);  p = fmaf(p, w, 0.00134934322f);
        p = fmaf(p, w, -0.00367342844f);  p = fmaf(p, w, 0.00573950773f);
        p = fmaf(p, w, -0.0076224613f);   p = fmaf(p, w, 0.00943887047f);
        p = fmaf(p, w, 1.00167406f);      p = fmaf(p, w, 2.83297682f);
    }
    return p * x;
}

__device__ __forceinline__ float sigf(float x) { return 1.0f / (1.0f + expf(-x)); }

__device__ __forceinline__ float warp_sum(float v) {
    v += __shfl_down_sync(0xffffffffu, v, 16); v += __shfl_down_sync(0xffffffffu, v, 8);
    v += __shfl_down_sync(0xffffffffu, v, 4);  v += __shfl_down_sync(0xffffffffu, v, 2);
    v += __shfl_down_sync(0xffffffffu, v, 1);  return v;
}

__global__ void k_keys() {
    int t = threadIdx.x; if (t >= 64) return;
#if PARTITIONABLE
    unsigned kt0, kt1, e0, e1, r0, r1;
    tf2x32(0u, 42u, 0u, (unsigned)t, kt0, kt1);
    tf2x32(kt0, kt1, 0u, 0u, e0, e1);
    tf2x32(kt0, kt1, 0u, 1u, r0, r1);
    g_keys[t][0] = e0; g_keys[t][1] = e1; g_keys[t][2] = r0; g_keys[t][3] = r1;
#else
    unsigned kt0, kt1, o0, o1;
    int j = 2 * t;
    if (j < 64) { tf2x32(0u, 42u, (unsigned)j, (unsigned)(j + 64), o0, o1); kt0 = o0; }
    else        { tf2x32(0u, 42u, (unsigned)(j - 64), (unsigned)j, o0, o1); kt0 = o1; }
    j = 2 * t + 1;
    if (j < 64) { tf2x32(0u, 42u, (unsigned)j, (unsigned)(j + 64), o0, o1); kt1 = o0; }
    else        { tf2x32(0u, 42u, (unsigned)(j - 64), (unsigned)j, o0, o1); kt1 = o1; }
    unsigned a0, a1, b0, b1;
    tf2x32(kt0, kt1, 0u, 2u, a0, a1);
    tf2x32(kt0, kt1, 1u, 3u, b0, b1);
    g_keys[t][0] = a0; g_keys[t][1] = b0; g_keys[t][2] = a1; g_keys[t][3] = b1;
#endif
}

__global__ void k_gum() {
    int idx = blockIdx.x * 256 + threadIdx.x;
    int t = idx >> 15;
    int w = idx & 32767;
    int c = w >> 10, ib = w & 1023;
    int i = ib >> 5, b = ib & 31;
    unsigned n = (unsigned)(i * 1024 + b * 32 + c);
    float f = bits_to_unit(rbits32(g_keys[t][2], g_keys[t][3], n, 16384u));
    float u = (f == 0.0f) ? 1.17549435e-38f : f;
    g_gum[idx] = -logf(-logf(u));
}

__global__ void k_prep(const float* __restrict__ W_hh) {
    int idx = blockIdx.x * 256 + threadIdx.x;
    int k = idx & 255, gc = idx >> 8;
    int g = gc / 160, cg = gc % 160;
    int gate = cg >> 5, j = cg & 31;
    g_Wb[idx] = W_hh[(gate * 256 + g * 32 + j) * 256 + k];
}

__global__ void k_init(const float* __restrict__ h0, const float* __restrict__ c0) {
    int i = blockIdx.x * 256 + threadIdx.x;
    g_hbuf[0][i] = h0[i]; g_cbuf[0][i] = c0[i];
    if (i == 0) { g_barA = 0u; g_barG = 0u; }
}

__global__ void k_emb(const float* __restrict__ obs, const float* __restrict__ win,
                      const float* __restrict__ W_obs, const float* __restrict__ b_obs,
                      const float* __restrict__ W_act, const float* __restrict__ b_act,
                      const float* __restrict__ W_fc, const float* __restrict__ b_fc) {
    int row = blockIdx.x, t = row >> 5, b = row & 31, c = threadIdx.x;
    float acc;
    if (c < 128) {
        const float* x = obs + b * 4096 + t * 64;
        const float* w = W_obs + c * 64;
        acc = b_obs[c];
        #pragma unroll 8
        for (int e = 0; e < 64; e++) acc = fmaf(x[e], w[e], acc);
    } else {
        const float* x = win + b * 3200 + t * 50;
        const float* w = W_act + (c - 128) * 50;
        acc = b_act[c - 128];
        for (int e = 0; e < 50; e++) acc = fmaf(x[e], w[e], acc);
    }
    acc = fmaxf(acc, 0.0f);
    g_emb[row * 256 + c] = acc;
    float xf = warp_sum(acc * W_fc[256 + c]);
    __shared__ float sm[8];
    if ((c & 31) == 0) sm[c >> 5] = xf;
    __syncthreads();
    if (c == 0) {
        float s = 0.0f;
        for (int i = 0; i < 8; i++) s += sm[i];
        g_xf[row] = s + b_fc[0];
    }
}

__global__ void k_gemm0(const float* __restrict__ W, const float* __restrict__ b1,
                        const float* __restrict__ b2) {
    __shared__ float As[16][64], Bs[16][64];
    int tid = threadIdx.x;
    int colBase = blockIdx.x << 6, rowBase = blockIdx.y << 6;
    int lr = tid >> 2, lc = (tid & 3) << 2;
    const float* Ap = g_emb + (rowBase + lr) * 256 + lc;
    const float* Bp = W + (colBase + lr) * 256 + lc;
    float acc[4][4] = {};
    int tx = tid & 15, ty = tid >> 4;
    for (int k0 = 0; k0 < 256; k0 += 16) {
        float4 av = *(const float4*)(Ap + k0);
        float4 bv = *(const float4*)(Bp + k0);
        __syncthreads();
        As[lc][lr] = av.x; As[lc+1][lr] = av.y; As[lc+2][lr] = av.z; As[lc+3][lr] = av.w;
        Bs[lc][lr] = bv.x; Bs[lc+1][lr] = bv.y; Bs[lc+2][lr] = bv.z; Bs[lc+3][lr] = bv.w;
        __syncthreads();
        #pragma unroll
        for (int kk = 0; kk < 16; kk++) {
            float4 a = *(const float4*)&As[kk][ty << 2];
            float4 b = *(const float4*)&Bs[kk][tx << 2];
            acc[0][0]=fmaf(a.x,b.x,acc[0][0]); acc[0][1]=fmaf(a.x,b.y,acc[0][1]);
            acc[0][2]=fmaf(a.x,b.z,acc[0][2]); acc[0][3]=fmaf(a.x,b.w,acc[0][3]);
            acc[1][0]=fmaf(a.y,b.x,acc[1][0]); acc[1][1]=fmaf(a.y,b.y,acc[1][1]);
            acc[1][2]=fmaf(a.y,b.z,acc[1][2]); acc[1][3]=fmaf(a.y,b.w,acc[1][3]);
            acc[2][0]=fmaf(a.z,b.x,acc[2][0]); acc[2][1]=fmaf(a.z,b.y,acc[2][1]);
            acc[2][2]=fmaf(a.z,b.z,acc[2][2]); acc[2][3]=fmaf(a.z,b.w,acc[2][3]);
            acc[3][0]=fmaf(a.w,b.x,acc[3][0]); acc[3][1]=fmaf(a.w,b.y,acc[3][1]);
            acc[3][2]=fmaf(a.w,b.z,acc[3][2]); acc[3][3]=fmaf(a.w,b.w,acc[3][3]);
        }
    }
    int r0 = rowBase + (ty << 2), c0 = colBase + (tx << 2);
    #pragma unroll
    for (int i = 0; i < 4; i++)
        #pragma unroll
        for (int j = 0; j < 4; j++) {
            int cc = c0 + j;
            g_xw[(r0 + i) * 1280 + cc] = acc[i][j] + b1[cc] + b2[cc];
        }
}

// software grid barrier — all 128 blocks co-resident (1 block/SM)
__device__ __forceinline__ void gbar(unsigned target) {
    __syncthreads();
    if (threadIdx.x == 0) {
        __threadfence();
        if (atomicAdd(&g_barA, 1u) == 127u) {
            g_barA = 0u;
            __threadfence();
            atomicExch(&g_barG, target);
        } else {
            while (atomicAdd(&g_barG, 0u) < target) { __nanosleep(64); }
        }
        __threadfence();
    }
    __syncthreads();
}

// ===== persistent kernel: all 64 steps; resample prologue + GEMM (B smem-resident) + cell =====
__global__ __launch_bounds__(512, 1) void k_persist(const float* __restrict__ W_fc,
                                                    const float* __restrict__ W_lab,
                                                    float* __restrict__ out,
                                                    const float* __restrict__ b_lab) {
    extern __shared__ float smem[];
    float* Bsm = smem;                    // 256*BP = 41216
    float* Asm = smem + 41216;            // 2*16*64 = 2048
    float* sv  = smem + 43264;
    float* sp1 = sv + 1024;
    float* slg = sp1 + 1024;
    float* spn = slg + 1024;
    float* ssv = spn + 1024;
    __shared__ int   sfl[1024];
    __shared__ float smx[32], sls[32], ss2[32];

    int tid = threadIdx.x;
    int g = blockIdx.x;
    int rowBase = blockIdx.y << 6;
    int bid = (blockIdx.y << 3) + blockIdx.x;
    int w = tid >> 5, j = tid & 31;
    int hc = (g << 5) + j;
    float wfc = W_fc[hc], wlb = W_lab[hc];
    float bl = b_lab[0];

    // load this block's W_hh slice into resident smem (transposed to [k][col])
    {
        const float* Wb = g_Wb + g * 40960;
        for (int idx = tid; idx < 40960; idx += 512) {
            int cg = idx >> 8, k = idx & 255;
            Bsm[k * BP + cg] = Wb[idx];
        }
    }

    int lrow = tid >> 2, lkc = (tid & 3) << 2;

    // eps bits for step 0
    unsigned ebits[4];
    {
        unsigned ke0 = g_keys[0][0], ke1 = g_keys[0][1];
        #pragma unroll
        for (int r = 0; r < 4; r++) {
            int kb = rowBase + (w << 2) + r;
            ebits[r] = rbits32(ke0, ke1, (unsigned)(kb * 256 + hc), 131072u);
        }
    }

    for (int t = 0; t <= 64; t++) {
        int ib = t & 1, ob = ib ^ 1;

        // ---------- prologue: resample step s = t-1 ----------
        if (t > 0) {
            int s = t - 1;
            int dp = s & 1;
            #pragma unroll
            for (int q = 0; q < 2; q++) {
                int kb = tid + (q << 9);
                float d1 = 0.0f, d2 = 0.0f;
                #pragma unroll
                for (int gg = 0; gg < 8; gg++) {
                    d1 += g_d1[dp][(gg << 10) + kb];
                    d2 += g_d2[dp][(gg << 10) + kb];
                }
                float pprev = (s == 0) ? -3.4657359027997265f : g_pbuf[(s - 1) & 1][kb];
                float v = (d1 + g_xf[s * 32 + (kb & 31)]) + pprev;
                sv[kb] = v; ssv[kb] = d2;
            }
            __syncthreads();
            // --- log-softmax over K: parallel max tree (exact) + parallel exp + serial sum ---
            slg[tid] = fmaxf(sv[(w << 6) + j], sv[(w << 6) + 32 + j]);   // pairwise max k={2w,2w+1}
            __syncthreads();
            if (tid < 32) {
                float m = slg[tid];
                #pragma unroll
                for (int k = 1; k < 16; k++) m = fmaxf(m, slg[k * 32 + tid]);
                smx[tid] = m;
            }
            __syncthreads();
            #pragma unroll
            for (int q = 0; q < 2; q++) {
                int kb = tid + (q << 9);
                spn[kb] = expf(sv[kb] - smx[kb & 31]);   // parallel exp (exact same inputs)
            }
            __syncthreads();
            if (tid < 32) {
                float sum = 0.0f;
                for (int k = 0; k < 32; k++) sum += spn[k * 32 + tid];   // original k-order
                sls[tid] = logf(sum);
            }
            __syncthreads();
            #pragma unroll
            for (int q = 0; q < 2; q++) {
                int kb = tid + (q << 9), b = kb & 31;
                float p1 = (sv[kb] - smx[b]) - sls[b];
                sp1[kb] = p1;
                slg[kb] = logf(0.5f * expf(p1) + 0.015625f);
            }
            __syncthreads();
            const float* gum = g_gum + s * 32768;
            #pragma unroll
            for (int q = 0; q < 2; q++) {
                int kb = tid + (q << 9), b = kb & 31;
                float best = -1e38f; int bi = 0;
                #pragma unroll 4
                for (int c = 0; c < 32; c++) {
                    float val = slg[c * 32 + b] + gum[c * 1024 + kb];
                    if (val > best) { best = val; bi = c; }
                }
                int fl = b + bi * 32;
                sfl[kb] = fl;
                float pu = expf(sp1[fl]);
                spn[kb] = logf(pu / (0.5f * pu + 0.015625f));
            }
            __syncthreads();
            // --- second log-softmax (weight renorm): same parallel structure ---
            sv[tid] = fmaxf(spn[(w << 6) + j], spn[(w << 6) + 32 + j]);
            __syncthreads();
            if (tid < 32) {
                float m = sv[tid];
                #pragma unroll
                for (int k = 1; k < 16; k++) m = fmaxf(m, sv[k * 32 + tid]);
                smx[tid] = m;
            }
            __syncthreads();
            #pragma unroll
            for (int q = 0; q < 2; q++) {
                int kb = tid + (q << 9);
                sp1[kb] = expf(spn[kb] - smx[kb & 31]);
            }
            __syncthreads();
            if (tid < 32) {
                float sum = 0.0f;
                for (int k = 0; k < 32; k++) sum += sp1[k * 32 + tid];   // original k-order
                ss2[tid] = logf(sum) + smx[tid];
            }
            __syncthreads();
            float pnn[2];
            #pragma unroll
            for (int q = 0; q < 2; q++) {
                int kb = tid + (q << 9), b = kb & 31;
                pnn[q] = spn[kb] - ss2[b];
                g_pbuf[s & 1][kb] = pnn[q];
            }
            __syncthreads();
            #pragma unroll
            for (int q = 0; q < 2; q++) {
                int kb = tid + (q << 9);
                spn[kb] = expf(pnn[q]);    // wexp for y_out (same expf values as before)
            }
            __syncthreads();
            // --- distributed outputs: pf_out 8/block, y_out col c on block 4c ---
            if (tid < 8) {
                int kb = (bid << 3) + tid;
                out[2048 + s * 1024 + kb] = 1.0f / (1.0f + expf(-(ssv[sfl[kb]] + bl)));
            }
            if ((bid & 3) == 0 && tid == 0) {
                int c = bid >> 2;
                float acc = 0.0f;
                for (int k = 0; k < 32; k++)
                    acc += spn[k * 32 + c] * ssv[sfl[k * 32 + c]];       // original k-order
                out[s * 32 + c] = 1.0f / (1.0f + expf(-(acc + bl)));
            }
        } else {
            sfl[tid] = tid; sfl[tid + 512] = tid + 512;
        }
        __syncthreads();

        if (t == 64) break;

        // ---------- prefetch epilogue operands (consumed after GEMM) ----------
        float pre_cp[4], pre_xw[4][5];
        {
            #pragma unroll
            for (int r = 0; r < 4; r++) {
                int kb = rowBase + (w << 2) + r;
                int b = kb & 31;
                const float* xw = g_xw + (t * 32 + b) * 1280;
                pre_cp[r]  = g_cbuf[ib][sfl[kb] * 256 + hc];
                #pragma unroll
                for (int gg = 0; gg < 5; gg++) pre_xw[r][gg] = xw[gg * 256 + hc];
            }
        }

        // ---------- recurrent GEMM: A staged (gathered), B resident in smem ----------
        const float* Ab = g_hbuf[ib] + sfl[rowBase + lrow] * 256 + lkc;   // tid<256 use
        float4 aP = make_float4(0, 0, 0, 0);
        if (tid < 256) {
            aP = *(const float4*)(Ab);
            Asm[(lkc + 0) * 64 + lrow] = aP.x; Asm[(lkc + 1) * 64 + lrow] = aP.y;
            Asm[(lkc + 2) * 64 + lrow] = aP.z; Asm[(lkc + 3) * 64 + lrow] = aP.w;
        }
        __syncthreads();

        float acc[4][5] = {};
        for (int kt = 0; kt < 16; kt++) {
            int buf = kt & 1;
            if (kt < 15 && tid < 256) aP = *(const float4*)(Ab + ((kt + 1) << 4));
            const float* Bk = Bsm + (kt << 4) * BP;
            const float* Ak = Asm + buf * 1024;
            #pragma unroll
            for (int kk = 0; kk < 16; kk++) {
                float4 a = *(const float4*)&Ak[kk * 64 + (w << 2)];
                float b0 = Bk[kk * BP + j];
                float b1 = Bk[kk * BP + 32 + j];
                float b2 = Bk[kk * BP + 64 + j];
                float b3 = Bk[kk * BP + 96 + j];
                float b4 = Bk[kk * BP + 128 + j];
                float av[4] = {a.x, a.y, a.z, a.w};
                #pragma unroll
                for (int r = 0; r < 4; r++) {
                    acc[r][0] = fmaf(av[r], b0, acc[r][0]);
                    acc[r][1] = fmaf(av[r], b1, acc[r][1]);
                    acc[r][2] = fmaf(av[r], b2, acc[r][2]);
                    acc[r][3] = fmaf(av[r], b3, acc[r][3]);
                    acc[r][4] = fmaf(av[r], b4, acc[r][4]);
                }
            }
            if (kt < 15) {
                __syncthreads();
                int nb = buf ^ 1;
                if (tid < 256) {
                    float* An = Asm + nb * 1024;
                    An[(lkc + 0) * 64 + lrow] = aP.x; An[(lkc + 1) * 64 + lrow] = aP.y;
                    An[(lkc + 2) * 64 + lrow] = aP.z; An[(lkc + 3) * 64 + lrow] = aP.w;
                }
                __syncthreads();
            }
        }

        // ---------- fused LSTM cell epilogue ----------
        int wp = t & 1;
        #pragma unroll
        for (int r = 0; r < 4; r++) {
            int kb = rowBase + (w << 2) + r;
            float gi = acc[r][0] + pre_xw[r][0];
            float gf = acc[r][1] + pre_xw[r][1];
            float gg = acc[r][2] + pre_xw[r][2];
            float go = acc[r][3] + pre_xw[r][3];
            float gv = acc[r][4] + pre_xw[r][4];
            float c1 = sigf(gf) * pre_cp[r] + sigf(gi) * tanhf(gg);
            float sp = fmaxf(gv, 0.0f) + log1pf(expf(-fabsf(gv)));
            float f01 = bits_to_unit(ebits[r]);
            float u = fmaxf(-0.99999994f, __fadd_rn(__fmul_rn(f01, 1.99999994f), -0.99999994f));
            float eps = 1.41421356f * xla_erfinv(u);
            c1 += eps * sp;
            float h1 = sigf(go) * tanhf(c1);
            g_hbuf[ob][kb * 256 + hc] = h1;
            g_cbuf[ob][kb * 256 + hc] = c1;
            float d1 = warp_sum(h1 * wfc);
            float d2 = warp_sum(h1 * wlb);
            if (j == 0) { g_d1[wp][(g << 10) + kb] = d1; g_d2[wp][(g << 10) + kb] = d2; }
        }

        // eps bits for step t+1 (before barrier; data-independent)
        if (t < 63) {
            unsigned ke0 = g_keys[t + 1][0], ke1 = g_keys[t + 1][1];
            #pragma unroll
            for (int r = 0; r < 4; r++) {
                int kb = rowBase + (w << 2) + r;
                ebits[r] = rbits32(ke0, ke1, (unsigned)(kb * 256 + hc), 131072u);
            }
        }

        gbar((unsigned)(t + 1));
    }
}

extern "C" void kernel_launch(void* const* d_in, const int* in_sizes, int n_in,
                              void* d_out, int out_size) {
    const float* obs    = (const float*)d_in[0];
    const float* win    = (const float*)d_in[1];
    const float* W_obs  = (const float*)d_in[2];
    const float* b_obs  = (const float*)d_in[3];
    const float* W_act  = (const float*)d_in[4];
    const float* b_act  = (const float*)d_in[5];
    const float* W_ih   = (const float*)d_in[6];
    const float* b_ih   = (const float*)d_in[7];
    const float* W_hh   = (const float*)d_in[8];
    const float* b_hh   = (const float*)d_in[9];
    const float* W_fc   = (const float*)d_in[10];
    const float* b_fc   = (const float*)d_in[11];
    const float* W_lab  = (const float*)d_in[12];
    const float* b_lab  = (const float*)d_in[13];
    const float* h0     = (const float*)d_in[14];
    const float* c0     = (const float*)d_in[15];
    float* out = (float*)d_out;

    size_t smem_bytes = (size_t)(41216 + 2048 + 5 * 1024) * sizeof(float);   // 193536
    cudaFuncSetAttribute(k_persist, cudaFuncAttributeMaxDynamicSharedMemorySize,
                         (int)smem_bytes);

    k_keys<<<1, 64>>>();
    k_init<<<1024, 256>>>(h0, c0);
    k_gum<<<8192, 256>>>();
    k_prep<<<1280, 256>>>(W_hh);
    k_emb<<<2048, 256>>>(obs, win, W_obs, b_obs, W_act, b_act, W_fc, b_fc);
    k_gemm0<<<dim3(20, 32), 256>>>(W_ih, b_ih, b_hh);
    k_persist<<<dim3(8, 16), 512, smem_bytes>>>(W_fc, W_lab, out, b_lab);
}